// round 12
// baseline (speedup 1.0000x reference)
#include <cuda_runtime.h>
#include <cuda_bf16.h>
#include <cstdint>
#include <cstddef>

// ----------------------------------------------------------------------------
// Problem constants (HetGraphModel)
// ----------------------------------------------------------------------------
#define N_NODES  100000
#define N_EDGES  500000
#define N_REL    3
#define N_LAYERS 2
#define F_IN     300
#define H_DIM    256
#define C_OUT    23
#define NR3      (N_REL * N_NODES)      // 300000
#define E3       (N_REL * N_EDGES)      // 1500000

// ----------------------------------------------------------------------------
// Scratch (device globals — no allocation allowed)
// ----------------------------------------------------------------------------
__device__ __align__(16) float g_h   [(size_t)N_NODES * H_DIM];
__device__ __align__(16) float g_res [(size_t)N_NODES * H_DIM];
__device__ __align__(16) float g_m   [(size_t)N_NODES * H_DIM];
__device__ __align__(16) float g_mcat[(size_t)N_NODES * H_DIM * N_REL];
__device__ __align__(16) float g_rs_out[NR3];
__device__ __align__(16) float g_rs_in [NR3];
// 4 BN instances: feat, layer0, layer1, head-c1.  stat: [sum(256), sumsq(256)]
__device__ __align__(16) float g_stat[4 * 512];
__device__ __align__(16) float g_aff [4 * 512];   // [a(256), b(256)]
__device__ __align__(16) float g_bsum[N_LAYERS * H_DIM];
// CSR scratch
__device__ __align__(16) int g_cnt[2 * NR3];
__device__ __align__(16) int g_rowstart[NR3 + 4];
__device__ __align__(16) int g_cursor[NR3];
__device__ __align__(16) int g_eidx[E3];
__device__ __align__(16) int g_bscan[512];
// K-major bf16 hi/lo weight planes
//   feat 256x320 ; skip[l] 256x256 ; gcn_cat[l] 256x768 ; c1 256x256
#define WT_FEAT    0
#define WT_SKIP(l) (81920 + (l) * 65536)
#define WT_GCN(l)  (212992 + (l) * 196608)
#define WT_C1      606208
#define WT_TOTAL   671744
__device__ __align__(16) __nv_bfloat16 g_wth[WT_TOTAL];
__device__ __align__(16) __nv_bfloat16 g_wtl[WT_TOTAL];

// ----------------------------------------------------------------------------
// PTX helpers
// ----------------------------------------------------------------------------
__device__ __forceinline__ uint32_t smem_u32(const void* p) {
    uint32_t a;
    asm("{ .reg .u64 t; cvta.to.shared.u64 t, %1; cvt.u32.u64 %0, t; }"
        : "=r"(a) : "l"(p));
    return a;
}
__device__ __forceinline__ void ldsm_x4(uint32_t* r, uint32_t addr) {
    asm volatile("ldmatrix.sync.aligned.m8n8.x4.shared.b16 {%0,%1,%2,%3}, [%4];"
                 : "=r"(r[0]), "=r"(r[1]), "=r"(r[2]), "=r"(r[3]) : "r"(addr));
}
__device__ __forceinline__ void mma_bf16(float* d, const uint32_t* a,
                                         uint32_t b0, uint32_t b1) {
    asm volatile(
        "mma.sync.aligned.m16n8k16.row.col.f32.bf16.bf16.f32 "
        "{%0,%1,%2,%3}, {%4,%5,%6,%7}, {%8,%9}, {%0,%1,%2,%3};"
        : "+f"(d[0]), "+f"(d[1]), "+f"(d[2]), "+f"(d[3])
        : "r"(a[0]), "r"(a[1]), "r"(a[2]), "r"(a[3]), "r"(b0), "r"(b1));
}
__device__ __forceinline__ void cp_async16(uint32_t saddr, const void* g) {
    asm volatile("cp.async.cg.shared.global [%0], [%1], 16;" :: "r"(saddr), "l"(g));
}
__device__ __forceinline__ void cp_commit() {
    asm volatile("cp.async.commit_group;");
}
template <int NN>
__device__ __forceinline__ void cp_wait() {
    asm volatile("cp.async.wait_group %0;" :: "n"(NN));
}
__device__ __forceinline__ void red_f32(float* p, float v) {
    asm volatile("red.global.add.f32 [%0], %1;" :: "l"(p), "f"(v) : "memory");
}
__device__ __forceinline__ void split4(float4 v, uint2& hi, uint2& lo) {
    __nv_bfloat162 h0 = __floats2bfloat162_rn(v.x, v.y);
    __nv_bfloat162 h1 = __floats2bfloat162_rn(v.z, v.w);
    float rx = v.x - __bfloat162float(h0.x);
    float ry = v.y - __bfloat162float(h0.y);
    float rz = v.z - __bfloat162float(h1.x);
    float rw = v.w - __bfloat162float(h1.y);
    __nv_bfloat162 l0 = __floats2bfloat162_rn(rx, ry);
    __nv_bfloat162 l1 = __floats2bfloat162_rn(rz, rw);
    hi = make_uint2(*reinterpret_cast<uint32_t*>(&h0), *reinterpret_cast<uint32_t*>(&h1));
    lo = make_uint2(*reinterpret_cast<uint32_t*>(&l0), *reinterpret_cast<uint32_t*>(&l1));
}
__device__ __forceinline__ float actf(float v, int act) {
    if (act == 1) return fmaxf(v, 0.f);
    if (act == 2) return (v > 0.f) ? v : 0.01f * v;
    return v;
}

// ----------------------------------------------------------------------------
// mma.sync GEMM:
//   C[M,256] = rowwise( actA(aff, A)[M,K] @ Wt[256,Kpad]^T + bias )
//   optional: C = out*scale + resid ; optional epilogue col-stats into stat.
//   Wt given as bf16 hi/lo planes (K-major). bf16 3-term split MMA.
// ----------------------------------------------------------------------------
#define MMA_TB   512
#define MMA_BM   128
#define MMA_BN   256
#define MMA_BK   32
#define AST      40
#define A_AREA   (4 * MMA_BM * AST)     // bf16 elements
#define B_AREA   (4 * MMA_BN * AST)
#define MMA_SMEM ((A_AREA + B_AREA) * 2)

__device__ __forceinline__ void prefA(const float* __restrict__ A,
                                      const float* __restrict__ aff, int act,
                                      int M, int K, int m0, int kc, int tid,
                                      float4* pa) {
#pragma unroll
    for (int i = 0; i < 2; i++) {
        int f = tid + i * MMA_TB;
        int row = f >> 3, c4 = f & 7;
        int gr = m0 + row, kg = kc + c4 * 4;
        float4 v = make_float4(0.f, 0.f, 0.f, 0.f);
        if (gr < M && kg + 4 <= K) {
            v = *reinterpret_cast<const float4*>(A + (size_t)gr * K + kg);
            if (aff) {
                const float4 aA = reinterpret_cast<const float4*>(aff)[kg >> 2];
                const float4 aB = reinterpret_cast<const float4*>(aff)[64 + (kg >> 2)];
                v.x = actf(fmaf(aA.x, v.x, aB.x), act);
                v.y = actf(fmaf(aA.y, v.y, aB.y), act);
                v.z = actf(fmaf(aA.z, v.z, aB.z), act);
                v.w = actf(fmaf(aA.w, v.w, aB.w), act);
            }
        }
        pa[i] = v;
    }
}

__global__ __launch_bounds__(MMA_TB)
void k_gemm_mma(const float* __restrict__ A,
                const __nv_bfloat16* __restrict__ Wth,
                const __nv_bfloat16* __restrict__ Wtl,
                const float* __restrict__ bias, float* __restrict__ C,
                int M, int K, int Kpad,
                const float* __restrict__ resid, float scale,
                const float* __restrict__ aff, int act,
                float* __restrict__ stat) {
    extern __shared__ __align__(16) __nv_bfloat16 sm[];
    __nv_bfloat16* As = sm;

    const int tid  = threadIdx.x;
    const int wid  = tid >> 5;
    const int lane = tid & 31;
    const int m0   = blockIdx.x * MMA_BM;
    const int wm   = (wid >> 3) * 64;
    const int wn   = (wid & 7) * 32;
    const uint32_t su = smem_u32(sm);
    const int lrow = lane & 15;
    const int lseg = lane >> 4;

    float acc[4][4][4];
#pragma unroll
    for (int i = 0; i < 4; i++)
#pragma unroll
        for (int j = 0; j < 4; j++)
#pragma unroll
            for (int q = 0; q < 4; q++) acc[i][j][q] = 0.f;

    const int NCH = Kpad / MMA_BK;

    // issue B cp.async for chunk c into buffer b
    auto issueB = [&](int c, int b) {
#pragma unroll
        for (int i = 0; i < 2; i++) {
            int t = tid + i * MMA_TB;      // 0..1023
            int n = t >> 2, seg = t & 3;
            size_t goff = (size_t)n * Kpad + c * MMA_BK + seg * 8;
            uint32_t d0 = su + 2u * (A_AREA + ((b * 2 + 0) * MMA_BN + n) * AST + seg * 8);
            uint32_t d1 = su + 2u * (A_AREA + ((b * 2 + 1) * MMA_BN + n) * AST + seg * 8);
            cp_async16(d0, Wth + goff);
            cp_async16(d1, Wtl + goff);
        }
        cp_commit();
    };
    auto storeA = [&](const float4* pa, int b) {
#pragma unroll
        for (int i = 0; i < 2; i++) {
            int f = tid + i * MMA_TB;
            int row = f >> 3, c4 = f & 7;
            uint2 hi, lo;
            split4(pa[i], hi, lo);
            int base = row * AST + c4 * 4;
            *reinterpret_cast<uint2*>(As + (b * 2 + 0) * MMA_BM * AST + base) = hi;
            *reinterpret_cast<uint2*>(As + (b * 2 + 1) * MMA_BM * AST + base) = lo;
        }
    };

    float4 pa[2];
    // pre-loop: chunk 0 staged into buf 0; prefetch chunk 1 into regs
    prefA(A, aff, act, M, K, m0, 0, tid, pa);
    issueB(0, 0);
    storeA(pa, 0);
    if (NCH > 1) prefA(A, aff, act, M, K, m0, MMA_BK, tid, pa);

    for (int c = 0; c < NCH; c++) {
        const int b = c & 1;
        __syncthreads();                    // compute(c-1) done -> b^1 reusable
        if (c + 1 < NCH) {
            issueB(c + 1, b ^ 1);
            storeA(pa, b ^ 1);
            if (c + 2 < NCH) prefA(A, aff, act, M, K, m0, (c + 2) * MMA_BK, tid, pa);
            cp_wait<1>();                   // chunk c's B complete
        } else {
            cp_wait<0>();
        }
        __syncthreads();                    // staged data visible to all

        // compute chunk c from buffer b
#pragma unroll
        for (int ks = 0; ks < 2; ks++) {
            const uint32_t klane = (uint32_t)(ks * 16 + lseg * 8);
            uint32_t af[4][4], bh[2][4], bl[2][4];
#pragma unroll
            for (int mt = 0; mt < 4; mt++) {
                uint32_t addr = su + 2u * (((b * 2 + 0) * MMA_BM + wm + mt * 16 + lrow) * AST + klane);
                ldsm_x4(af[mt], addr);
            }
#pragma unroll
            for (int p = 0; p < 2; p++) {
                uint32_t addr = su + 2u * (A_AREA + ((b * 2 + 0) * MMA_BN + wn + p * 16 + lrow) * AST + klane);
                ldsm_x4(bh[p], addr);
            }
#pragma unroll
            for (int p = 0; p < 2; p++) {
                uint32_t addr = su + 2u * (A_AREA + ((b * 2 + 1) * MMA_BN + wn + p * 16 + lrow) * AST + klane);
                ldsm_x4(bl[p], addr);
            }
#pragma unroll
            for (int mt = 0; mt < 4; mt++)
#pragma unroll
                for (int nt = 0; nt < 4; nt++) {
                    int p = nt >> 1, o = nt & 1;
                    mma_bf16(acc[mt][nt], af[mt], bh[p][o], bh[p][o + 2]);
                    mma_bf16(acc[mt][nt], af[mt], bl[p][o], bl[p][o + 2]);
                }
#pragma unroll
            for (int mt = 0; mt < 4; mt++) {
                uint32_t addr = su + 2u * (((b * 2 + 1) * MMA_BM + wm + mt * 16 + lrow) * AST + klane);
                ldsm_x4(af[mt], addr);
            }
#pragma unroll
            for (int mt = 0; mt < 4; mt++)
#pragma unroll
                for (int nt = 0; nt < 4; nt++) {
                    int p = nt >> 1, o = nt & 1;
                    mma_bf16(acc[mt][nt], af[mt], bh[p][o], bh[p][o + 2]);
                }
        }
    }

    // --- epilogue (+ optional col-stats) ---
    const int qrow = lane >> 2;
    const int qcol = (lane & 3) * 2;
    float s[8], s2[8];
#pragma unroll
    for (int j = 0; j < 8; j++) { s[j] = 0.f; s2[j] = 0.f; }

#pragma unroll
    for (int mt = 0; mt < 4; mt++) {
        int r0 = m0 + wm + mt * 16 + qrow;
        int r1 = r0 + 8;
#pragma unroll
        for (int nt = 0; nt < 4; nt++) {
            int cc = wn + nt * 8 + qcol;
            float b0 = bias[cc], b1 = bias[cc + 1];
            if (r0 < M) {
                size_t idx = (size_t)r0 * MMA_BN + cc;
                float2 v = make_float2(acc[mt][nt][0] + b0, acc[mt][nt][1] + b1);
                if (resid) {
                    const float2 rr = *reinterpret_cast<const float2*>(resid + idx);
                    v.x = v.x * scale + rr.x; v.y = v.y * scale + rr.y;
                }
                *reinterpret_cast<float2*>(C + idx) = v;
                if (stat) {
                    s[nt * 2]     += v.x; s2[nt * 2]     += v.x * v.x;
                    s[nt * 2 + 1] += v.y; s2[nt * 2 + 1] += v.y * v.y;
                }
            }
            if (r1 < M) {
                size_t idx = (size_t)r1 * MMA_BN + cc;
                float2 v = make_float2(acc[mt][nt][2] + b0, acc[mt][nt][3] + b1);
                if (resid) {
                    const float2 rr = *reinterpret_cast<const float2*>(resid + idx);
                    v.x = v.x * scale + rr.x; v.y = v.y * scale + rr.y;
                }
                *reinterpret_cast<float2*>(C + idx) = v;
                if (stat) {
                    s[nt * 2]     += v.x; s2[nt * 2]     += v.x * v.x;
                    s[nt * 2 + 1] += v.y; s2[nt * 2 + 1] += v.y * v.y;
                }
            }
        }
    }
    if (stat) {
#pragma unroll
        for (int j = 0; j < 8; j++) {
#pragma unroll
            for (int off = 4; off < 32; off <<= 1) {
                s[j]  += __shfl_xor_sync(0xFFFFFFFFu, s[j],  off);
                s2[j] += __shfl_xor_sync(0xFFFFFFFFu, s2[j], off);
            }
        }
        if (qrow == 0) {
#pragma unroll
            for (int j = 0; j < 8; j++) {
                int cc = wn + (j >> 1) * 8 + qcol + (j & 1);
                red_f32(&stat[cc], s[j]);
                red_f32(&stat[256 + cc], s2[j]);
            }
        }
    }
}

// ----------------------------------------------------------------------------
// One fused weight transpose+split kernel (all slots)
// ----------------------------------------------------------------------------
__global__ void k_transpose_all(const float* __restrict__ W_feat,
                                const float* __restrict__ skip_W,
                                const float* __restrict__ gcn_W,
                                const float* __restrict__ W_c1,
                                __nv_bfloat16* __restrict__ wth,
                                __nv_bfloat16* __restrict__ wtl) {
    int e = blockIdx.x * blockDim.x + threadIdx.x;
    if (e >= WT_TOTAL) return;
    float x;
    if (e < 81920) {                        // feat: Kpad=320, K=300
        int n = e / 320, k = e % 320;
        x = (k < F_IN) ? W_feat[(size_t)k * H_DIM + n] : 0.f;
    } else if (e < 212992) {                // skip[l]
        int e2 = e - 81920;
        int l = e2 / 65536, r = e2 % 65536;
        int n = r / 256, k = r % 256;
        x = skip_W[((size_t)l * 256 + k) * 256 + n];
    } else if (e < 606208) {                // gcn_cat[l]: Kpad=768
        int e3 = e - 212992;
        int l = e3 / 196608, r = e3 % 196608;
        int n = r / 768, kk = r % 768;
        int rel = kk / 256, k = kk % 256;
        x = gcn_W[(((size_t)l * N_REL + rel) * 256 + k) * 256 + n];
    } else {                                 // c1
        int e4 = e - 606208;
        int n = e4 / 256, k = e4 % 256;
        x = W_c1[(size_t)k * 256 + n];
    }
    __nv_bfloat16 hi = __float2bfloat16_rn(x);
    wth[e] = hi;
    wtl[e] = __float2bfloat16_rn(x - __bfloat162float(hi));
}

// stat -> per-column affine (a, b):  y = a*x + b
__global__ void k_mkaff(const float* __restrict__ stat, const float* __restrict__ g,
                        const float* __restrict__ b, float* __restrict__ aff) {
    int c = threadIdx.x;
    const float invM = 1.f / (float)N_NODES;
    float mean = stat[c] * invM;
    float var  = stat[256 + c] * invM - mean * mean;
    float a = g[c] * rsqrtf(var + 1e-5f);
    aff[c] = a;
    aff[256 + c] = b[c] - a * mean;
}

// ----------------------------------------------------------------------------
// CSR build + gather
// ----------------------------------------------------------------------------
__global__ void k_zero4(float4* __restrict__ p, int n4) {
    int i = blockIdx.x * blockDim.x + threadIdx.x;
    if (i < n4) p[i] = make_float4(0.f, 0.f, 0.f, 0.f);
}

__global__ void k_hist(const int* __restrict__ esrc, const int* __restrict__ edst,
                       int* __restrict__ cnt) {
    int i = blockIdx.x * blockDim.x + threadIdx.x;
    if (i < E3) {
        int r = i / N_EDGES;
        atomicAdd(&cnt[r * N_NODES + edst[i]], 1);
        atomicAdd(&cnt[NR3 + r * N_NODES + esrc[i]], 1);
    }
}

__global__ void k_scan1(const int* __restrict__ in, int* __restrict__ out,
                        int* __restrict__ bsum, int n) {
    __shared__ int ts[256];
    int tid = threadIdx.x;
    int base = blockIdx.x * 1024 + tid * 4;
    int v[4];
#pragma unroll
    for (int q = 0; q < 4; q++) v[q] = (base + q < n) ? in[base + q] : 0;
    int tot = v[0] + v[1] + v[2] + v[3];
    ts[tid] = tot;
    __syncthreads();
    for (int off = 1; off < 256; off <<= 1) {
        int x = (tid >= off) ? ts[tid - off] : 0;
        __syncthreads();
        ts[tid] += x;
        __syncthreads();
    }
    int run = ts[tid] - tot;
#pragma unroll
    for (int q = 0; q < 4; q++) {
        if (base + q < n) out[base + q] = run;
        run += v[q];
    }
    if (tid == 255) bsum[blockIdx.x] = ts[255];
}

__global__ void k_scan2(int* __restrict__ bsum, int nb) {
    __shared__ int sb[512];
    int tid = threadIdx.x;
    int orig = (tid < nb) ? bsum[tid] : 0;
    sb[tid] = orig;
    __syncthreads();
    for (int off = 1; off < 512; off <<= 1) {
        int x = (tid >= off) ? sb[tid - off] : 0;
        __syncthreads();
        sb[tid] += x;
        __syncthreads();
    }
    if (tid < nb) bsum[tid] = sb[tid] - orig;
}

__global__ void k_scan3(int* __restrict__ rowstart, const int* __restrict__ bsum,
                        const int* __restrict__ cnt, int* __restrict__ cursor,
                        float* __restrict__ rsin, float* __restrict__ rsout) {
    int i = blockIdx.x * blockDim.x + threadIdx.x;
    if (i < NR3) {
        int v = rowstart[i] + bsum[i >> 10];
        rowstart[i] = v;
        cursor[i]   = v;
        rsin[i]  = rsqrtf((float)max(cnt[i], 1));
        rsout[i] = rsqrtf((float)max(cnt[NR3 + i], 1));
    }
    if (i == 0) rowstart[NR3] = E3;
}

__global__ void k_fill(const int* __restrict__ esrc, const int* __restrict__ edst,
                       int* __restrict__ cursor, int* __restrict__ eidx) {
    int i = blockIdx.x * blockDim.x + threadIdx.x;
    if (i < E3) {
        int r = i / N_EDGES;
        int pos = atomicAdd(&cursor[r * N_NODES + edst[i]], 1);
        eidx[pos] = esrc[i];
    }
}

// One warp per (relation, node); applies BN-affine+act to h on the fly.
__global__ __launch_bounds__(256)
void k_gather(const int* __restrict__ rowstart, const int* __restrict__ eidx,
              const float* __restrict__ rsout, const float* __restrict__ rsin,
              const float* __restrict__ h, const float* __restrict__ aff, int act,
              float* __restrict__ mcat) {
    int w = (blockIdx.x * blockDim.x + threadIdx.x) >> 5;
    if (w >= NR3) return;
    int lane = threadIdx.x & 31;
    int r = w / N_NODES;
    int n = w - r * N_NODES;
    int j0 = rowstart[w], j1 = rowstart[w + 1];

    const float4 aA0 = reinterpret_cast<const float4*>(aff)[lane];
    const float4 aA1 = reinterpret_cast<const float4*>(aff)[lane + 32];
    const float4 aB0 = reinterpret_cast<const float4*>(aff)[64 + lane];
    const float4 aB1 = reinterpret_cast<const float4*>(aff)[64 + lane + 32];

    float4 a = make_float4(0.f, 0.f, 0.f, 0.f);
    float4 bb = make_float4(0.f, 0.f, 0.f, 0.f);
    const float4* h4 = reinterpret_cast<const float4*>(h);
    const float* rso = rsout + r * N_NODES;
    for (int j = j0; j < j1; j++) {
        int s = eidx[j];
        float sc = rso[s];
        const float4* hr = h4 + (size_t)s * 64;
        float4 u = hr[lane];
        float4 v = hr[lane + 32];
        u.x = actf(fmaf(aA0.x, u.x, aB0.x), act);
        u.y = actf(fmaf(aA0.y, u.y, aB0.y), act);
        u.z = actf(fmaf(aA0.z, u.z, aB0.z), act);
        u.w = actf(fmaf(aA0.w, u.w, aB0.w), act);
        v.x = actf(fmaf(aA1.x, v.x, aB1.x), act);
        v.y = actf(fmaf(aA1.y, v.y, aB1.y), act);
        v.z = actf(fmaf(aA1.z, v.z, aB1.z), act);
        v.w = actf(fmaf(aA1.w, v.w, aB1.w), act);
        a.x += sc * u.x; a.y += sc * u.y; a.z += sc * u.z; a.w += sc * u.w;
        bb.x += sc * v.x; bb.y += sc * v.y; bb.z += sc * v.z; bb.w += sc * v.w;
    }
    float sn = rsin[w];
    float4* o4 = reinterpret_cast<float4*>(mcat) + (size_t)n * 192 + r * 64;
    o4[lane]      = make_float4(a.x * sn, a.y * sn, a.z * sn, a.w * sn);
    o4[lane + 32] = make_float4(bb.x * sn, bb.y * sn, bb.z * sn, bb.w * sn);
}

// bsum[l][c] = sum_r gcn_b[l][r][c]
__global__ void k_bias_sum(const float* __restrict__ gcn_b, float* __restrict__ bsum) {
    int i = blockIdx.x * blockDim.x + threadIdx.x;
    if (i < N_LAYERS * H_DIM) {
        int l = i / H_DIM, c = i - l * H_DIM;
        float s = 0.f;
        for (int r = 0; r < N_REL; r++) s += gcn_b[(l * N_REL + r) * H_DIM + c];
        bsum[i] = s;
    }
}

// ----------------------------------------------------------------------------
// SIMT GEMM for the tiny C_OUT=23 head (A gets BN-affine + act)
// ----------------------------------------------------------------------------
template <int BN_, int TN_>
__global__ __launch_bounds__(256, 2)
void k_gemm(const float* __restrict__ A, const float* __restrict__ W,
            const float* __restrict__ bias, float* __restrict__ C,
            int M, int K, int Nout, const float* __restrict__ aff, int act) {
    constexpr int BM = 128;
    constexpr int BK = 16;
    constexpr int TM = 8;
    __shared__ float As[BK][BM + 4];
    __shared__ float Bs[BK][BN_ + 4];
    const int tid = threadIdx.x;
    const int tx = tid & 15;
    const int ty = tid >> 4;
    const int m0 = blockIdx.y * BM;
    const int n0 = blockIdx.x * BN_;
    float acc[TM][TN_];
#pragma unroll
    for (int i = 0; i < TM; i++)
#pragma unroll
        for (int j = 0; j < TN_; j++) acc[i][j] = 0.f;
    for (int k0 = 0; k0 < K; k0 += BK) {
#pragma unroll
        for (int t = 0; t < (BM * BK) / 256; t++) {
            int lin = tid + t * 256;
            int row = lin >> 4, kk = lin & 15;
            int gr = m0 + row, gk = k0 + kk;
            float v = 0.f;
            if (gr < M && gk < K) {
                v = A[(size_t)gr * K + gk];
                v = actf(fmaf(aff[gk], v, aff[256 + gk]), act);
            }
            As[kk][row] = v;
        }
#pragma unroll
        for (int t = 0; t < (BN_ * BK) / 256; t++) {
            int lin = tid + t * 256;
            int kr = lin / BN_, col = lin % BN_;
            int gk = k0 + kr, gc = n0 + col;
            Bs[kr][col] = (gk < K && gc < Nout) ? W[(size_t)gk * Nout + gc] : 0.f;
        }
        __syncthreads();
#pragma unroll
        for (int kk = 0; kk < BK; kk++) {
            float ra[TM], rb[TN_];
#pragma unroll
            for (int i = 0; i < TM; i++) ra[i] = As[kk][ty * TM + i];
#pragma unroll
            for (int j = 0; j < TN_; j++) rb[j] = Bs[kk][tx * TN_ + j];
#pragma unroll
            for (int i = 0; i < TM; i++)
#pragma unroll
                for (int j = 0; j < TN_; j++) acc[i][j] += ra[i] * rb[j];
        }
        __syncthreads();
    }
#pragma unroll
    for (int i = 0; i < TM; i++) {
        int gr = m0 + ty * TM + i;
        if (gr >= M) continue;
#pragma unroll
        for (int j = 0; j < TN_; j++) {
            int gc = n0 + tx * TN_ + j;
            if (gc >= Nout) continue;
            C[(size_t)gr * Nout + gc] = acc[i][j] + bias[gc];
        }
    }
}

// ----------------------------------------------------------------------------
// Host orchestration
// ----------------------------------------------------------------------------
static inline void zero4(float* p, size_t n) {
    int n4 = (int)(n / 4);
    k_zero4<<<(n4 + 255) / 256, 256>>>((float4*)p, n4);
}

static inline void run_mma(const float* A, const __nv_bfloat16* Wth,
                           const __nv_bfloat16* Wtl, const float* bias,
                           float* C, int M, int K, int Kpad,
                           const float* resid, float scale,
                           const float* aff, int act, float* stat) {
    k_gemm_mma<<<(M + MMA_BM - 1) / MMA_BM, MMA_TB, MMA_SMEM>>>(
        A, Wth, Wtl, bias, C, M, K, Kpad, resid, scale, aff, act, stat);
}

extern "C" void kernel_launch(void* const* d_in, const int* in_sizes, int n_in,
                              void* d_out, int out_size) {
    (void)in_sizes; (void)n_in; (void)out_size;
    const float* x         = (const float*)d_in[0];
    const int*   esrc      = (const int*)  d_in[1];
    const int*   edst      = (const int*)  d_in[2];
    const float* W_feat    = (const float*)d_in[3];
    const float* b_feat    = (const float*)d_in[4];
    const float* g_feat    = (const float*)d_in[5];
    const float* beta_feat = (const float*)d_in[6];
    const float* gcn_W     = (const float*)d_in[7];
    const float* gcn_b     = (const float*)d_in[8];
    const float* skip_W    = (const float*)d_in[9];
    const float* skip_b    = (const float*)d_in[10];
    const float* bn_g      = (const float*)d_in[11];
    const float* bn_b      = (const float*)d_in[12];
    const float* W_c1      = (const float*)d_in[13];
    const float* b_c1      = (const float*)d_in[14];
    const float* g_c       = (const float*)d_in[15];
    const float* beta_c    = (const float*)d_in[16];
    const float* W_c2      = (const float*)d_in[17];
    const float* b_c2      = (const float*)d_in[18];
    float* out = (float*)d_out;

    cudaFuncSetAttribute(k_gemm_mma, cudaFuncAttributeMaxDynamicSharedMemorySize, MMA_SMEM);

    float *h, *res, *m, *mcat, *rsout, *rsin, *stat, *aff, *bsumf;
    __nv_bfloat16 *wth, *wtl;
    int *cnt, *rowstart, *cursor, *eidx, *bscan;
    cudaGetSymbolAddress((void**)&h,     g_h);
    cudaGetSymbolAddress((void**)&res,   g_res);
    cudaGetSymbolAddress((void**)&m,     g_m);
    cudaGetSymbolAddress((void**)&mcat,  g_mcat);
    cudaGetSymbolAddress((void**)&rsout, g_rs_out);
    cudaGetSymbolAddress((void**)&rsin,  g_rs_in);
    cudaGetSymbolAddress((void**)&stat,  g_stat);
    cudaGetSymbolAddress((void**)&aff,   g_aff);
    cudaGetSymbolAddress((void**)&bsumf, g_bsum);
    cudaGetSymbolAddress((void**)&wth,   g_wth);
    cudaGetSymbolAddress((void**)&wtl,   g_wtl);
    cudaGetSymbolAddress((void**)&cnt,      g_cnt);
    cudaGetSymbolAddress((void**)&rowstart, g_rowstart);
    cudaGetSymbolAddress((void**)&cursor,   g_cursor);
    cudaGetSymbolAddress((void**)&eidx,     g_eidx);
    cudaGetSymbolAddress((void**)&bscan,    g_bscan);

    // --- weight prep + stat zero + CSR build ---
    k_transpose_all<<<(WT_TOTAL + 255) / 256, 256>>>(W_feat, skip_W, gcn_W, W_c1, wth, wtl);
    k_bias_sum<<<(N_LAYERS * H_DIM + 255) / 256, 256>>>(gcn_b, bsumf);
    zero4(stat, 4 * 512);
    zero4((float*)cnt, 2 * NR3);
    k_hist<<<(E3 + 255) / 256, 256>>>(esrc, edst, cnt);
    const int nb = (NR3 + 1023) / 1024;
    k_scan1<<<nb, 256>>>(cnt, rowstart, bscan, NR3);
    k_scan2<<<1, 512>>>(bscan, nb);
    k_scan3<<<(NR3 + 255) / 256, 256>>>(rowstart, bscan, cnt, cursor, rsin, rsout);
    k_fill<<<(E3 + 255) / 256, 256>>>(esrc, edst, cursor, eidx);

    // --- feat_reduce GEMM (stats -> slot 0), then affine 0 ---
    run_mma(x, wth + WT_FEAT, wtl + WT_FEAT, b_feat, h, N_NODES, F_IN, 320,
            nullptr, 1.f, nullptr, 0, stat + 0 * 512);
    k_mkaff<<<1, 256>>>(stat + 0 * 512, g_feat, beta_feat, aff + 0 * 512);

    // --- layers ---
    const int gather_blocks = (NR3 * 32 + 255) / 256;
    const float* affp = aff + 0 * 512;
    int actp = 1;   // relu after feat BN
    for (int l = 0; l < N_LAYERS; l++) {
        run_mma(h, wth + WT_SKIP(l), wtl + WT_SKIP(l), skip_b + l * H_DIM, res,
                N_NODES, H_DIM, H_DIM, nullptr, 1.f, affp, actp, nullptr);
        k_gather<<<gather_blocks, 256>>>(rowstart, eidx, rsout, rsin, h, affp, actp, mcat);
        run_mma(mcat, wth + WT_GCN(l), wtl + WT_GCN(l), bsumf + l * H_DIM, h,
                N_NODES, N_REL * H_DIM, N_REL * H_DIM, res, 1.f / 3.f,
                nullptr, 0, stat + (1 + l) * 512);
        k_mkaff<<<1, 256>>>(stat + (1 + l) * 512, bn_g + l * H_DIM, bn_b + l * H_DIM,
                            aff + (1 + l) * 512);
        affp = aff + (1 + l) * 512;
        actp = 2;   // leaky relu after layer BN
    }

    // --- head ---
    run_mma(h, wth + WT_C1, wtl + WT_C1, b_c1, m, N_NODES, H_DIM, H_DIM,
            nullptr, 1.f, affp, actp, stat + 3 * 512);
    k_mkaff<<<1, 256>>>(stat + 3 * 512, g_c, beta_c, aff + 3 * 512);
    k_gemm<64, 4><<<dim3(1, (N_NODES + 127) / 128), 256>>>(
        m, W_c2, b_c2, out, N_NODES, H_DIM, C_OUT, aff + 3 * 512, 1);
}

// round 13
// speedup vs baseline: 1.2024x; 1.2024x over previous
#include <cuda_runtime.h>
#include <cuda_bf16.h>
#include <cstdint>
#include <cstddef>

// ----------------------------------------------------------------------------
// Problem constants (HetGraphModel)
// ----------------------------------------------------------------------------
#define N_NODES  100000
#define N_EDGES  500000
#define N_REL    3
#define N_LAYERS 2
#define F_IN     300
#define H_DIM    256
#define C_OUT    23
#define NR3      (N_REL * N_NODES)      // 300000
#define E3       (N_REL * N_EDGES)      // 1500000

// ----------------------------------------------------------------------------
// Scratch (device globals — no allocation allowed)
// ----------------------------------------------------------------------------
__device__ __align__(16) float g_h   [(size_t)N_NODES * H_DIM];
__device__ __align__(16) float g_hact[(size_t)N_NODES * H_DIM];
__device__ __align__(16) float g_m   [(size_t)N_NODES * H_DIM];
__device__ __align__(16) float g_mcat[(size_t)N_NODES * H_DIM * N_REL];
__device__ __align__(16) float g_rs_out[NR3];
__device__ __align__(16) float g_rs_in [NR3];
// 4 BN instances: feat, layer0, layer1, head-c1.  stat: [sum(256), sumsq(256)]
__device__ __align__(16) float g_stat[4 * 512];
__device__ __align__(16) float g_aff [4 * 512];   // [a(256), b(256)]
__device__ __align__(16) float g_bcomb[N_LAYERS * H_DIM];
// CSR scratch
__device__ __align__(16) int g_cnt[2 * NR3];
__device__ __align__(16) int g_rowstart[NR3 + 4];
__device__ __align__(16) int g_cursor[NR3];
__device__ __align__(16) int g_eidx[E3];
__device__ __align__(16) int g_bscan[512];
// K-major bf16 hi/lo weight planes:
//   feat 256x320 ; layer_cat[l] 256x1024 = [gcn/3 (768) | skip (256)] ; c1 256x256
#define WT_FEAT    0
#define WT_LAY(l)  (81920 + (l) * 262144)
#define WT_C1      606208
#define WT_TOTAL   671744
__device__ __align__(16) __nv_bfloat16 g_wth[WT_TOTAL];
__device__ __align__(16) __nv_bfloat16 g_wtl[WT_TOTAL];

// ----------------------------------------------------------------------------
// PTX helpers
// ----------------------------------------------------------------------------
__device__ __forceinline__ uint32_t smem_u32(const void* p) {
    uint32_t a;
    asm("{ .reg .u64 t; cvta.to.shared.u64 t, %1; cvt.u32.u64 %0, t; }"
        : "=r"(a) : "l"(p));
    return a;
}
__device__ __forceinline__ void ldsm_x4(uint32_t* r, uint32_t addr) {
    asm volatile("ldmatrix.sync.aligned.m8n8.x4.shared.b16 {%0,%1,%2,%3}, [%4];"
                 : "=r"(r[0]), "=r"(r[1]), "=r"(r[2]), "=r"(r[3]) : "r"(addr));
}
__device__ __forceinline__ void mma_bf16(float* d, const uint32_t* a,
                                         uint32_t b0, uint32_t b1) {
    asm volatile(
        "mma.sync.aligned.m16n8k16.row.col.f32.bf16.bf16.f32 "
        "{%0,%1,%2,%3}, {%4,%5,%6,%7}, {%8,%9}, {%0,%1,%2,%3};"
        : "+f"(d[0]), "+f"(d[1]), "+f"(d[2]), "+f"(d[3])
        : "r"(a[0]), "r"(a[1]), "r"(a[2]), "r"(a[3]), "r"(b0), "r"(b1));
}
__device__ __forceinline__ void cp_async16(uint32_t saddr, const void* g) {
    asm volatile("cp.async.cg.shared.global [%0], [%1], 16;" :: "r"(saddr), "l"(g));
}
__device__ __forceinline__ void cp_commit() {
    asm volatile("cp.async.commit_group;");
}
template <int NN>
__device__ __forceinline__ void cp_wait() {
    asm volatile("cp.async.wait_group %0;" :: "n"(NN));
}
__device__ __forceinline__ void red_f32(float* p, float v) {
    asm volatile("red.global.add.f32 [%0], %1;" :: "l"(p), "f"(v) : "memory");
}
__device__ __forceinline__ void split4(float4 v, uint2& hi, uint2& lo) {
    __nv_bfloat162 h0 = __floats2bfloat162_rn(v.x, v.y);
    __nv_bfloat162 h1 = __floats2bfloat162_rn(v.z, v.w);
    float rx = v.x - __bfloat162float(h0.x);
    float ry = v.y - __bfloat162float(h0.y);
    float rz = v.z - __bfloat162float(h1.x);
    float rw = v.w - __bfloat162float(h1.y);
    __nv_bfloat162 l0 = __floats2bfloat162_rn(rx, ry);
    __nv_bfloat162 l1 = __floats2bfloat162_rn(rz, rw);
    hi = make_uint2(*reinterpret_cast<uint32_t*>(&h0), *reinterpret_cast<uint32_t*>(&h1));
    lo = make_uint2(*reinterpret_cast<uint32_t*>(&l0), *reinterpret_cast<uint32_t*>(&l1));
}
__device__ __forceinline__ float actf(float v, int act) {
    if (act == 1) return fmaxf(v, 0.f);
    if (act == 2) return (v > 0.f) ? v : 0.01f * v;
    return v;
}

// ----------------------------------------------------------------------------
// mma.sync GEMM with split A source:
//   Arow(k) = A1[row][k]           for k in [0, K1)   (A1 row stride = K1)
//           = A2[row][k - K1]      for k in [K1,...)  (A2 row stride = 256)
//           = 0                    where out of range (zero-pad to Kpad)
//   C[M,256] = Arow @ Wt[256,Kpad]^T + bias ; col-stats (sum, sumsq) -> stat.
//   Wt given as bf16 hi/lo planes (K-major). bf16 3-term split MMA.
// ----------------------------------------------------------------------------
#define MMA_TB   512
#define MMA_BM   128
#define MMA_BN   256
#define MMA_BK   32
#define AST      40
#define A_AREA   (4 * MMA_BM * AST)     // bf16 elements
#define B_AREA   (4 * MMA_BN * AST)
#define MMA_SMEM ((A_AREA + B_AREA) * 2)

__global__ __launch_bounds__(MMA_TB)
void k_gemm_mma(const float* __restrict__ A1, int K1,
                const float* __restrict__ A2,
                const __nv_bfloat16* __restrict__ Wth,
                const __nv_bfloat16* __restrict__ Wtl,
                const float* __restrict__ bias, float* __restrict__ C,
                int M, int Kpad, float* __restrict__ stat) {
    extern __shared__ __align__(16) __nv_bfloat16 sm[];
    __nv_bfloat16* As = sm;

    const int tid  = threadIdx.x;
    const int wid  = tid >> 5;
    const int lane = tid & 31;
    const int m0   = blockIdx.x * MMA_BM;
    const int wm   = (wid >> 3) * 64;
    const int wn   = (wid & 7) * 32;
    const uint32_t su = smem_u32(sm);
    const int lrow = lane & 15;
    const int lseg = lane >> 4;

    float acc[4][4][4];
#pragma unroll
    for (int i = 0; i < 4; i++)
#pragma unroll
        for (int j = 0; j < 4; j++)
#pragma unroll
            for (int q = 0; q < 4; q++) acc[i][j][q] = 0.f;

    const int NCH = Kpad / MMA_BK;

    auto prefA = [&](int kc, float4* pa) {
#pragma unroll
        for (int i = 0; i < 2; i++) {
            int f = tid + i * MMA_TB;
            int row = f >> 3, c4 = f & 7;
            int gr = m0 + row, kg = kc + c4 * 4;
            float4 v = make_float4(0.f, 0.f, 0.f, 0.f);
            if (gr < M) {
                if (kg + 4 <= K1)
                    v = *reinterpret_cast<const float4*>(A1 + (size_t)gr * K1 + kg);
                else if (A2 && kg >= K1)
                    v = *reinterpret_cast<const float4*>(A2 + (size_t)gr * 256 + (kg - K1));
            }
            pa[i] = v;
        }
    };
    auto issueB = [&](int c, int b) {
#pragma unroll
        for (int i = 0; i < 2; i++) {
            int t = tid + i * MMA_TB;      // 0..1023
            int n = t >> 2, seg = t & 3;
            size_t goff = (size_t)n * Kpad + c * MMA_BK + seg * 8;
            uint32_t d0 = su + 2u * (A_AREA + ((b * 2 + 0) * MMA_BN + n) * AST + seg * 8);
            uint32_t d1 = su + 2u * (A_AREA + ((b * 2 + 1) * MMA_BN + n) * AST + seg * 8);
            cp_async16(d0, Wth + goff);
            cp_async16(d1, Wtl + goff);
        }
        cp_commit();
    };
    auto storeA = [&](const float4* pa, int b) {
#pragma unroll
        for (int i = 0; i < 2; i++) {
            int f = tid + i * MMA_TB;
            int row = f >> 3, c4 = f & 7;
            uint2 hi, lo;
            split4(pa[i], hi, lo);
            int base = row * AST + c4 * 4;
            *reinterpret_cast<uint2*>(As + (b * 2 + 0) * MMA_BM * AST + base) = hi;
            *reinterpret_cast<uint2*>(As + (b * 2 + 1) * MMA_BM * AST + base) = lo;
        }
    };

    float4 pa[2];
    prefA(0, pa);
    issueB(0, 0);
    storeA(pa, 0);
    if (NCH > 1) prefA(MMA_BK, pa);

    for (int c = 0; c < NCH; c++) {
        const int b = c & 1;
        __syncthreads();                    // compute(c-1) done -> b^1 reusable
        if (c + 1 < NCH) {
            issueB(c + 1, b ^ 1);
            storeA(pa, b ^ 1);
            if (c + 2 < NCH) prefA((c + 2) * MMA_BK, pa);
            cp_wait<1>();                   // chunk c's B complete
        } else {
            cp_wait<0>();
        }
        __syncthreads();                    // staged data visible to all

#pragma unroll
        for (int ks = 0; ks < 2; ks++) {
            const uint32_t klane = (uint32_t)(ks * 16 + lseg * 8);
            uint32_t af[4][4], bh[2][4], bl[2][4];
#pragma unroll
            for (int mt = 0; mt < 4; mt++) {
                uint32_t addr = su + 2u * (((b * 2 + 0) * MMA_BM + wm + mt * 16 + lrow) * AST + klane);
                ldsm_x4(af[mt], addr);
            }
#pragma unroll
            for (int p = 0; p < 2; p++) {
                uint32_t addr = su + 2u * (A_AREA + ((b * 2 + 0) * MMA_BN + wn + p * 16 + lrow) * AST + klane);
                ldsm_x4(bh[p], addr);
            }
#pragma unroll
            for (int p = 0; p < 2; p++) {
                uint32_t addr = su + 2u * (A_AREA + ((b * 2 + 1) * MMA_BN + wn + p * 16 + lrow) * AST + klane);
                ldsm_x4(bl[p], addr);
            }
#pragma unroll
            for (int mt = 0; mt < 4; mt++)
#pragma unroll
                for (int nt = 0; nt < 4; nt++) {
                    int p = nt >> 1, o = nt & 1;
                    mma_bf16(acc[mt][nt], af[mt], bh[p][o], bh[p][o + 2]);
                    mma_bf16(acc[mt][nt], af[mt], bl[p][o], bl[p][o + 2]);
                }
#pragma unroll
            for (int mt = 0; mt < 4; mt++) {
                uint32_t addr = su + 2u * (((b * 2 + 1) * MMA_BM + wm + mt * 16 + lrow) * AST + klane);
                ldsm_x4(af[mt], addr);
            }
#pragma unroll
            for (int mt = 0; mt < 4; mt++)
#pragma unroll
                for (int nt = 0; nt < 4; nt++) {
                    int p = nt >> 1, o = nt & 1;
                    mma_bf16(acc[mt][nt], af[mt], bh[p][o], bh[p][o + 2]);
                }
        }
    }

    // --- epilogue + col-stats ---
    const int qrow = lane >> 2;
    const int qcol = (lane & 3) * 2;
    float s[8], s2[8];
#pragma unroll
    for (int j = 0; j < 8; j++) { s[j] = 0.f; s2[j] = 0.f; }

#pragma unroll
    for (int mt = 0; mt < 4; mt++) {
        int r0 = m0 + wm + mt * 16 + qrow;
        int r1 = r0 + 8;
#pragma unroll
        for (int nt = 0; nt < 4; nt++) {
            int cc = wn + nt * 8 + qcol;
            float b0 = bias[cc], b1 = bias[cc + 1];
            if (r0 < M) {
                float2 v = make_float2(acc[mt][nt][0] + b0, acc[mt][nt][1] + b1);
                *reinterpret_cast<float2*>(C + (size_t)r0 * MMA_BN + cc) = v;
                s[nt * 2]     += v.x; s2[nt * 2]     += v.x * v.x;
                s[nt * 2 + 1] += v.y; s2[nt * 2 + 1] += v.y * v.y;
            }
            if (r1 < M) {
                float2 v = make_float2(acc[mt][nt][2] + b0, acc[mt][nt][3] + b1);
                *reinterpret_cast<float2*>(C + (size_t)r1 * MMA_BN + cc) = v;
                s[nt * 2]     += v.x; s2[nt * 2]     += v.x * v.x;
                s[nt * 2 + 1] += v.y; s2[nt * 2 + 1] += v.y * v.y;
            }
        }
    }
#pragma unroll
    for (int j = 0; j < 8; j++) {
#pragma unroll
        for (int off = 4; off < 32; off <<= 1) {
            s[j]  += __shfl_xor_sync(0xFFFFFFFFu, s[j],  off);
            s2[j] += __shfl_xor_sync(0xFFFFFFFFu, s2[j], off);
        }
    }
    if (qrow == 0) {
#pragma unroll
        for (int j = 0; j < 8; j++) {
            int cc = wn + (j >> 1) * 8 + qcol + (j & 1);
            red_f32(&stat[cc], s[j]);
            red_f32(&stat[256 + cc], s2[j]);
        }
    }
}

// ----------------------------------------------------------------------------
// Fused weight transpose + bf16 hi/lo split (all slots, one launch)
//   layer_cat[l]: k<768 -> gcn_W[l][k/256][k%256][n] * (1/3) ; k>=768 -> skip_W[l][k-768][n]
// ----------------------------------------------------------------------------
__global__ void k_transpose_all(const float* __restrict__ W_feat,
                                const float* __restrict__ skip_W,
                                const float* __restrict__ gcn_W,
                                const float* __restrict__ W_c1,
                                __nv_bfloat16* __restrict__ wth,
                                __nv_bfloat16* __restrict__ wtl) {
    int e = blockIdx.x * blockDim.x + threadIdx.x;
    if (e >= WT_TOTAL) return;
    float x;
    if (e < 81920) {                        // feat: Kpad=320, K=300
        int n = e / 320, k = e % 320;
        x = (k < F_IN) ? W_feat[(size_t)k * H_DIM + n] : 0.f;
    } else if (e < 606208) {                // layer_cat[l]: Kpad=1024
        int e2 = e - 81920;
        int l = e2 / 262144, r = e2 % 262144;
        int n = r / 1024, k = r % 1024;
        if (k < 768) {
            int rel = k / 256, kk = k % 256;
            x = gcn_W[(((size_t)l * N_REL + rel) * 256 + kk) * 256 + n] * (1.f / 3.f);
        } else {
            x = skip_W[((size_t)l * 256 + (k - 768)) * 256 + n];
        }
    } else {                                 // c1: Kpad=256
        int e4 = e - 606208;
        int n = e4 / 256, k = e4 % 256;
        x = W_c1[(size_t)k * 256 + n];
    }
    __nv_bfloat16 hi = __float2bfloat16_rn(x);
    wth[e] = hi;
    wtl[e] = __float2bfloat16_rn(x - __bfloat162float(hi));
}

// bcomb[l][c] = sum_r gcn_b[l][r][c] / 3 + skip_b[l][c]
__global__ void k_bias_comb(const float* __restrict__ gcn_b,
                            const float* __restrict__ skip_b,
                            float* __restrict__ bc) {
    int i = blockIdx.x * blockDim.x + threadIdx.x;
    if (i < N_LAYERS * H_DIM) {
        int l = i / H_DIM, c = i - l * H_DIM;
        float s = 0.f;
        for (int r = 0; r < N_REL; r++) s += gcn_b[(l * N_REL + r) * H_DIM + c];
        bc[i] = s * (1.f / 3.f) + skip_b[i];
    }
}

// stat -> per-column affine (a, b):  y = a*x + b
__global__ void k_mkaff(const float* __restrict__ stat, const float* __restrict__ g,
                        const float* __restrict__ b, float* __restrict__ aff) {
    int c = threadIdx.x;
    const float invM = 1.f / (float)N_NODES;
    float mean = stat[c] * invM;
    float var  = stat[256 + c] * invM - mean * mean;
    float a = g[c] * rsqrtf(var + 1e-5f);
    aff[c] = a;
    aff[256 + c] = b[c] - a * mean;
}

// hact = act(a * h + b)  (vectorized)
__global__ void k_apply(const float4* __restrict__ h, const float* __restrict__ aff,
                        int act, float4* __restrict__ hact) {
    int i = blockIdx.x * blockDim.x + threadIdx.x;
    if (i >= N_NODES * (H_DIM / 4)) return;
    int c4 = i & 63;
    const float4 a = reinterpret_cast<const float4*>(aff)[c4];
    const float4 b = reinterpret_cast<const float4*>(aff)[64 + c4];
    float4 v = h[i];
    v.x = actf(fmaf(a.x, v.x, b.x), act);
    v.y = actf(fmaf(a.y, v.y, b.y), act);
    v.z = actf(fmaf(a.z, v.z, b.z), act);
    v.w = actf(fmaf(a.w, v.w, b.w), act);
    hact[i] = v;
}

// ----------------------------------------------------------------------------
// CSR build + gather
// ----------------------------------------------------------------------------
__global__ void k_zero4(float4* __restrict__ p, int n4) {
    int i = blockIdx.x * blockDim.x + threadIdx.x;
    if (i < n4) p[i] = make_float4(0.f, 0.f, 0.f, 0.f);
}

__global__ void k_hist(const int* __restrict__ esrc, const int* __restrict__ edst,
                       int* __restrict__ cnt) {
    int i = blockIdx.x * blockDim.x + threadIdx.x;
    if (i < E3) {
        int r = i / N_EDGES;
        atomicAdd(&cnt[r * N_NODES + edst[i]], 1);
        atomicAdd(&cnt[NR3 + r * N_NODES + esrc[i]], 1);
    }
}

__global__ void k_scan1(const int* __restrict__ in, int* __restrict__ out,
                        int* __restrict__ bsum, int n) {
    __shared__ int ts[256];
    int tid = threadIdx.x;
    int base = blockIdx.x * 1024 + tid * 4;
    int v[4];
#pragma unroll
    for (int q = 0; q < 4; q++) v[q] = (base + q < n) ? in[base + q] : 0;
    int tot = v[0] + v[1] + v[2] + v[3];
    ts[tid] = tot;
    __syncthreads();
    for (int off = 1; off < 256; off <<= 1) {
        int x = (tid >= off) ? ts[tid - off] : 0;
        __syncthreads();
        ts[tid] += x;
        __syncthreads();
    }
    int run = ts[tid] - tot;
#pragma unroll
    for (int q = 0; q < 4; q++) {
        if (base + q < n) out[base + q] = run;
        run += v[q];
    }
    if (tid == 255) bsum[blockIdx.x] = ts[255];
}

__global__ void k_scan2(int* __restrict__ bsum, int nb) {
    __shared__ int sb[512];
    int tid = threadIdx.x;
    int orig = (tid < nb) ? bsum[tid] : 0;
    sb[tid] = orig;
    __syncthreads();
    for (int off = 1; off < 512; off <<= 1) {
        int x = (tid >= off) ? sb[tid - off] : 0;
        __syncthreads();
        sb[tid] += x;
        __syncthreads();
    }
    if (tid < nb) bsum[tid] = sb[tid] - orig;
}

__global__ void k_scan3(int* __restrict__ rowstart, const int* __restrict__ bsum,
                        const int* __restrict__ cnt, int* __restrict__ cursor,
                        float* __restrict__ rsin, float* __restrict__ rsout) {
    int i = blockIdx.x * blockDim.x + threadIdx.x;
    if (i < NR3) {
        int v = rowstart[i] + bsum[i >> 10];
        rowstart[i] = v;
        cursor[i]   = v;
        rsin[i]  = rsqrtf((float)max(cnt[i], 1));
        rsout[i] = rsqrtf((float)max(cnt[NR3 + i], 1));
    }
    if (i == 0) rowstart[NR3] = E3;
}

__global__ void k_fill(const int* __restrict__ esrc, const int* __restrict__ edst,
                       int* __restrict__ cursor, int* __restrict__ eidx) {
    int i = blockIdx.x * blockDim.x + threadIdx.x;
    if (i < E3) {
        int r = i / N_EDGES;
        int pos = atomicAdd(&cursor[r * N_NODES + edst[i]], 1);
        eidx[pos] = esrc[i];
    }
}

// One warp per (relation, node): mcat[n][r*256+c] = rs_in * sum_e rs_out[src] * hact[src][c]
__global__ __launch_bounds__(256)
void k_gather(const int* __restrict__ rowstart, const int* __restrict__ eidx,
              const float* __restrict__ rsout, const float* __restrict__ rsin,
              const float* __restrict__ h, float* __restrict__ mcat) {
    int w = (blockIdx.x * blockDim.x + threadIdx.x) >> 5;
    if (w >= NR3) return;
    int lane = threadIdx.x & 31;
    int r = w / N_NODES;
    int n = w - r * N_NODES;
    int j0 = rowstart[w], j1 = rowstart[w + 1];
    float4 a = make_float4(0.f, 0.f, 0.f, 0.f);
    float4 bb = make_float4(0.f, 0.f, 0.f, 0.f);
    const float4* h4 = reinterpret_cast<const float4*>(h);
    const float* rso = rsout + r * N_NODES;
    for (int j = j0; j < j1; j++) {
        int s = eidx[j];
        float sc = rso[s];
        const float4* hr = h4 + (size_t)s * 64;
        float4 u = hr[lane];
        float4 v = hr[lane + 32];
        a.x += sc * u.x; a.y += sc * u.y; a.z += sc * u.z; a.w += sc * u.w;
        bb.x += sc * v.x; bb.y += sc * v.y; bb.z += sc * v.z; bb.w += sc * v.w;
    }
    float sn = rsin[w];
    float4* o4 = reinterpret_cast<float4*>(mcat) + (size_t)n * 192 + r * 64;
    o4[lane]      = make_float4(a.x * sn, a.y * sn, a.z * sn, a.w * sn);
    o4[lane + 32] = make_float4(bb.x * sn, bb.y * sn, bb.z * sn, bb.w * sn);
}

// ----------------------------------------------------------------------------
// SIMT GEMM for the tiny C_OUT=23 head (A gets BN-affine + relu)
// ----------------------------------------------------------------------------
template <int BN_, int TN_>
__global__ __launch_bounds__(256, 2)
void k_gemm(const float* __restrict__ A, const float* __restrict__ W,
            const float* __restrict__ bias, float* __restrict__ C,
            int M, int K, int Nout, const float* __restrict__ aff, int act) {
    constexpr int BM = 128;
    constexpr int BK = 16;
    constexpr int TM = 8;
    __shared__ float As[BK][BM + 4];
    __shared__ float Bs[BK][BN_ + 4];
    const int tid = threadIdx.x;
    const int tx = tid & 15;
    const int ty = tid >> 4;
    const int m0 = blockIdx.y * BM;
    const int n0 = blockIdx.x * BN_;
    float acc[TM][TN_];
#pragma unroll
    for (int i = 0; i < TM; i++)
#pragma unroll
        for (int j = 0; j < TN_; j++) acc[i][j] = 0.f;
    for (int k0 = 0; k0 < K; k0 += BK) {
#pragma unroll
        for (int t = 0; t < (BM * BK) / 256; t++) {
            int lin = tid + t * 256;
            int row = lin >> 4, kk = lin & 15;
            int gr = m0 + row, gk = k0 + kk;
            float v = 0.f;
            if (gr < M && gk < K) {
                v = A[(size_t)gr * K + gk];
                v = actf(fmaf(aff[gk], v, aff[256 + gk]), act);
            }
            As[kk][row] = v;
        }
#pragma unroll
        for (int t = 0; t < (BN_ * BK) / 256; t++) {
            int lin = tid + t * 256;
            int kr = lin / BN_, col = lin % BN_;
            int gk = k0 + kr, gc = n0 + col;
            Bs[kr][col] = (gk < K && gc < Nout) ? W[(size_t)gk * Nout + gc] : 0.f;
        }
        __syncthreads();
#pragma unroll
        for (int kk = 0; kk < BK; kk++) {
            float ra[TM], rb[TN_];
#pragma unroll
            for (int i = 0; i < TM; i++) ra[i] = As[kk][ty * TM + i];
#pragma unroll
            for (int j = 0; j < TN_; j++) rb[j] = Bs[kk][tx * TN_ + j];
#pragma unroll
            for (int i = 0; i < TM; i++)
#pragma unroll
                for (int j = 0; j < TN_; j++) acc[i][j] += ra[i] * rb[j];
        }
        __syncthreads();
    }
#pragma unroll
    for (int i = 0; i < TM; i++) {
        int gr = m0 + ty * TM + i;
        if (gr >= M) continue;
#pragma unroll
        for (int j = 0; j < TN_; j++) {
            int gc = n0 + tx * TN_ + j;
            if (gc >= Nout) continue;
            C[(size_t)gr * Nout + gc] = acc[i][j] + bias[gc];
        }
    }
}

// ----------------------------------------------------------------------------
// Host orchestration
// ----------------------------------------------------------------------------
static inline void zero4(float* p, size_t n) {
    int n4 = (int)(n / 4);
    k_zero4<<<(n4 + 255) / 256, 256>>>((float4*)p, n4);
}

static inline void run_mma(const float* A1, int K1, const float* A2,
                           const __nv_bfloat16* Wth, const __nv_bfloat16* Wtl,
                           const float* bias, float* C, int M, int Kpad,
                           float* stat) {
    k_gemm_mma<<<(M + MMA_BM - 1) / MMA_BM, MMA_TB, MMA_SMEM>>>(
        A1, K1, A2, Wth, Wtl, bias, C, M, Kpad, stat);
}

extern "C" void kernel_launch(void* const* d_in, const int* in_sizes, int n_in,
                              void* d_out, int out_size) {
    (void)in_sizes; (void)n_in; (void)out_size;
    const float* x         = (const float*)d_in[0];
    const int*   esrc      = (const int*)  d_in[1];
    const int*   edst      = (const int*)  d_in[2];
    const float* W_feat    = (const float*)d_in[3];
    const float* b_feat    = (const float*)d_in[4];
    const float* g_feat    = (const float*)d_in[5];
    const float* beta_feat = (const float*)d_in[6];
    const float* gcn_W     = (const float*)d_in[7];
    const float* gcn_b     = (const float*)d_in[8];
    const float* skip_W    = (const float*)d_in[9];
    const float* skip_b    = (const float*)d_in[10];
    const float* bn_g      = (const float*)d_in[11];
    const float* bn_b      = (const float*)d_in[12];
    const float* W_c1      = (const float*)d_in[13];
    const float* b_c1      = (const float*)d_in[14];
    const float* g_c       = (const float*)d_in[15];
    const float* beta_c    = (const float*)d_in[16];
    const float* W_c2      = (const float*)d_in[17];
    const float* b_c2      = (const float*)d_in[18];
    float* out = (float*)d_out;

    cudaFuncSetAttribute(k_gemm_mma, cudaFuncAttributeMaxDynamicSharedMemorySize, MMA_SMEM);

    float *h, *hact, *m, *mcat, *rsout, *rsin, *stat, *aff, *bcomb;
    __nv_bfloat16 *wth, *wtl;
    int *cnt, *rowstart, *cursor, *eidx, *bscan;
    cudaGetSymbolAddress((void**)&h,     g_h);
    cudaGetSymbolAddress((void**)&hact,  g_hact);
    cudaGetSymbolAddress((void**)&m,     g_m);
    cudaGetSymbolAddress((void**)&mcat,  g_mcat);
    cudaGetSymbolAddress((void**)&rsout, g_rs_out);
    cudaGetSymbolAddress((void**)&rsin,  g_rs_in);
    cudaGetSymbolAddress((void**)&stat,  g_stat);
    cudaGetSymbolAddress((void**)&aff,   g_aff);
    cudaGetSymbolAddress((void**)&bcomb, g_bcomb);
    cudaGetSymbolAddress((void**)&wth,   g_wth);
    cudaGetSymbolAddress((void**)&wtl,   g_wtl);
    cudaGetSymbolAddress((void**)&cnt,      g_cnt);
    cudaGetSymbolAddress((void**)&rowstart, g_rowstart);
    cudaGetSymbolAddress((void**)&cursor,   g_cursor);
    cudaGetSymbolAddress((void**)&eidx,     g_eidx);
    cudaGetSymbolAddress((void**)&bscan,    g_bscan);

    const int NH4 = N_NODES * (H_DIM / 4);

    // --- weight prep + stat zero + CSR build ---
    k_transpose_all<<<(WT_TOTAL + 255) / 256, 256>>>(W_feat, skip_W, gcn_W, W_c1, wth, wtl);
    k_bias_comb<<<(N_LAYERS * H_DIM + 255) / 256, 256>>>(gcn_b, skip_b, bcomb);
    zero4(stat, 4 * 512);
    zero4((float*)cnt, 2 * NR3);
    k_hist<<<(E3 + 255) / 256, 256>>>(esrc, edst, cnt);
    const int nb = (NR3 + 1023) / 1024;
    k_scan1<<<nb, 256>>>(cnt, rowstart, bscan, NR3);
    k_scan2<<<1, 512>>>(bscan, nb);
    k_scan3<<<(NR3 + 255) / 256, 256>>>(rowstart, bscan, cnt, cursor, rsin, rsout);
    k_fill<<<(E3 + 255) / 256, 256>>>(esrc, edst, cursor, eidx);

    // --- feat_reduce GEMM (stats -> slot 0), affine, activation ---
    run_mma(x, F_IN, nullptr, wth + WT_FEAT, wtl + WT_FEAT, b_feat, h,
            N_NODES, 320, stat + 0 * 512);
    k_mkaff<<<1, 256>>>(stat + 0 * 512, g_feat, beta_feat, aff + 0 * 512);
    k_apply<<<(NH4 + 255) / 256, 256>>>((const float4*)h, aff + 0 * 512, 1, (float4*)hact);

    // --- layers: gather + one fused [gcn/3 | skip] GEMM, K = 1024 ---
    const int gather_blocks = (NR3 * 32 + 255) / 256;
    for (int l = 0; l < N_LAYERS; l++) {
        k_gather<<<gather_blocks, 256>>>(rowstart, eidx, rsout, rsin, hact, mcat);
        run_mma(mcat, N_REL * H_DIM, hact, wth + WT_LAY(l), wtl + WT_LAY(l),
                bcomb + l * H_DIM, h, N_NODES, 1024, stat + (1 + l) * 512);
        k_mkaff<<<1, 256>>>(stat + (1 + l) * 512, bn_g + l * H_DIM, bn_b + l * H_DIM,
                            aff + (1 + l) * 512);
        k_apply<<<(NH4 + 255) / 256, 256>>>((const float4*)h, aff + (1 + l) * 512, 2,
                                            (float4*)hact);
    }

    // --- head: c1 GEMM on activated input, then tiny classifier ---
    run_mma(hact, H_DIM, nullptr, wth + WT_C1, wtl + WT_C1, b_c1, m,
            N_NODES, 256, stat + 3 * 512);
    k_mkaff<<<1, 256>>>(stat + 3 * 512, g_c, beta_c, aff + 3 * 512);
    k_gemm<64, 4><<<dim3(1, (N_NODES + 127) / 128), 256>>>(
        m, W_c2, b_c2, out, N_NODES, H_DIM, C_OUT, aff + 3 * 512, 1);
}